// round 7
// baseline (speedup 1.0000x reference)
#include <cuda_runtime.h>
#include <cuda_fp16.h>
#include <stdint.h>

// ---------------------------------------------------------------------------
// TT-linear fused kernel, v7 = v6 with the stage-A swizzled-store offset fix
// (within-chunk byte offset 4c, was 8c). 4 i0-chunks (M=64 per chunk),
// XOR-swizzled T2 (stride 128 halves, no pad), 76KB smem -> 3 CTAs/SM.
// All mma.sync (tcgen05 unavailable: harness uses compute_103 virtual arch).
// ---------------------------------------------------------------------------

#define M1STR 136
#define M0STR 136
#define T1STR 40
#define YSTR  260

// half-offsets
#define H_M1 0
#define H_M0 17408
#define H_T2 19584          // 64 rows x 128 halves, XOR-swizzled
#define H_T1 27776          // 256 rows x T1STR
#define SMEM_HALVES (H_T1 + 256 * T1STR)   // 38016
#define SMEM_BYTES (SMEM_HALVES * 2)       // 76032

// byte offsets
#define B_M1 (H_M1 * 2)
#define B_M0 (H_M0 * 2)
#define B_T2 (H_T2 * 2)
#define B_T1 (H_T1 * 2)

// fp16 core matrices, pre-permuted:
//  g_M2[n=(o2*8+r2)][k]           (128 x 16), column k holds i2 = sigma(k)
//  g_M1[n=(o1*8+r1)][k=(i1*8+r2)] (128 x 128)
//  g_M0[n=o0][k=(i0*8+r1)]        (16 x 128)
__device__ __half g_M2[128 * 16];
__device__ __half g_M1[128 * 128];
__device__ __half g_M0[16 * 128];

__global__ void tt_prep_cores(const float* __restrict__ c0,
                              const float* __restrict__ c1,
                              const float* __restrict__ c2) {
    int t = blockIdx.x * blockDim.x + threadIdx.x;
    if (t < 128 * 16) {
        int n = t >> 4, k = t & 15;
        int o2 = n >> 3, r2 = n & 7;
        int cc = (k >> 1) & 3, d = k & 1, e = k >> 3;
        int i2 = 4 * cc + 2 * e + d;          // sigma(k)
        g_M2[t] = __float2half(c2[(r2 * 16 + o2) * 16 + i2]);
    }
    if (t < 128 * 128) {
        int n = t >> 7, k = t & 127;
        int o1 = n >> 3, r1 = n & 7;
        int i1 = k >> 3, r2 = k & 7;
        g_M1[t] = __float2half(c1[((r1 * 16 + o1) * 16 + i1) * 8 + r2]);
    }
    if (t < 16 * 128) {
        int n = t >> 7, k = t & 127;
        int i0 = k >> 3, r1 = k & 7;
        g_M0[t] = __float2half(c0[(n * 16 + i0) * 8 + r1]);
    }
}

__device__ __forceinline__ void mma16816(float* d, const uint32_t* a,
                                         uint32_t b0, uint32_t b1) {
    asm volatile(
        "mma.sync.aligned.m16n8k16.row.col.f32.f16.f16.f32 "
        "{%0,%1,%2,%3}, {%4,%5,%6,%7}, {%8,%9}, {%0,%1,%2,%3};\n"
        : "+f"(d[0]), "+f"(d[1]), "+f"(d[2]), "+f"(d[3])
        : "r"(a[0]), "r"(a[1]), "r"(a[2]), "r"(a[3]), "r"(b0), "r"(b1));
}

__device__ __forceinline__ void ldsm4(uint32_t* r, uint32_t addr) {
    asm volatile(
        "ldmatrix.sync.aligned.m8n8.x4.shared.b16 {%0,%1,%2,%3}, [%4];\n"
        : "=r"(r[0]), "=r"(r[1]), "=r"(r[2]), "=r"(r[3]) : "r"(addr));
}

__device__ __forceinline__ uint32_t packh2(float lo, float hi) {
    __half2 h = __floats2half2_rn(lo, hi);
    return *(uint32_t*)&h;
}

__global__ void __launch_bounds__(256, 3)
tt_linear_kernel(const float* __restrict__ x, const float* __restrict__ bias,
                 float* __restrict__ y) {
    extern __shared__ __half smem[];
    char* sc = (char*)smem;
    __half* T1c = smem + H_T1;
    float*  Ysm = (float*)(sc + B_T2);   // aliases T2+T1 head (dead at epilogue)

    const int b    = blockIdx.x;
    const int tid  = threadIdx.x;
    const int w    = tid >> 5;
    const int lane = tid & 31;
    const int g = lane >> 2, c = lane & 3;
    const int lsel = lane & 15;            // LDSM row select
    const int lhi8 = (lane >> 4) << 3;     // LDSM k half offset (halves)
    const int hi   = lane >> 4;            // LDSM k chunk (16B units)

    const int mw = w & 3;                  // stage A/B m-warp
    const int nw = w >> 2;                 // stage A/B n-warp

    uint32_t sbase;
    asm("{ .reg .u64 t; cvta.to.shared.u64 t, %1; cvt.u32.u64 %0, t; }"
        : "=r"(sbase) : "l"(smem));
    const uint32_t sM1 = sbase + B_M1;
    const uint32_t sM0 = sbase + B_M0;
    const uint32_t sT2 = sbase + B_T2;
    const uint32_t sT1 = sbase + B_T1;

    // ---- prologue: copy M1, M0 into smem (16B vectors) ----
    {
        const uint4* s1 = (const uint4*)g_M1;   // 2048 uint4
        #pragma unroll
        for (int i = 0; i < 8; i++) {
            int idx = tid + 256 * i;
            int n = idx >> 4, ch = idx & 15;
            *(uint4*)(sc + B_M1 + (n * M1STR + ch * 8) * 2) = s1[idx];
        }
        const uint4* s0 = (const uint4*)g_M0;   // 256 uint4
        int n = tid >> 4, ch = tid & 15;
        *(uint4*)(sc + B_M0 + (n * M0STR + ch * 8) * 2) = s0[tid];
    }

    const float* xr = x + (size_t)b * 4096;

    float accc[2][2][4];
    #pragma unroll
    for (int mi = 0; mi < 2; mi++)
        #pragma unroll
        for (int nt = 0; nt < 2; nt++)
            #pragma unroll
            for (int q = 0; q < 4; q++) accc[mi][nt][q] = 0.f;

    // ---- stage A: x chunk (4 i0 rows) @ M2^T -> swizzled T2 ----
    auto stageA = [&](int t) {
        // lane fragment rows i1 = g, g+8; li0 = mw
        const float* rp = xr + (4 * t + mw) * 256 + 16 * g + 4 * c;
        float4 f0 = *(const float4*)(rp);
        float4 f1 = *(const float4*)(rp + 128);
        uint32_t a[4];
        a[0] = packh2(f0.x, f0.y);
        a[1] = packh2(f1.x, f1.y);
        a[2] = packh2(f0.z, f0.w);
        a[3] = packh2(f1.z, f1.w);
        #pragma unroll
        for (int j = 0; j < 8; j++) {
            const int nt = 8 * nw + j;            // o2
            uint32_t b0 = *(const uint32_t*)&g_M2[(8 * nt + g) * 16 + 2 * c];
            uint32_t b1 = *(const uint32_t*)&g_M2[(8 * nt + g) * 16 + 2 * c + 8];
            float d[4] = {0.f, 0.f, 0.f, 0.f};
            mma16816(d, a, b0, b1);
            // T2 row = 16*mw + nt; cols (i1*8 + r2): chunks g and g+8,
            // within-chunk byte offset 4c, chunk swizzle ^ (row&7)
            char* rowp = sc + B_T2 + (16 * mw + nt) * 256 + 4 * c;
            const int sw = (g ^ (nt & 7)) << 4;
            *(half2*)(rowp + sw)       = __floats2half2_rn(d[0], d[1]);
            *(half2*)(rowp + sw + 128) = __floats2half2_rn(d[2], d[3]);
        }
    };

    // ---- stage B: T2 (64x128) @ M1^T -> scatter to T1 ----
    auto stageB = [&]() {
        float accb[8][4];
        #pragma unroll
        for (int j = 0; j < 8; j++)
            #pragma unroll
            for (int q = 0; q < 4; q++) accb[j][q] = 0.f;

        const int ar = 16 * mw + lsel;            // T2 row for this lane
        const uint32_t arbase = sT2 + ar * 256;
        const int ar7 = ar & 7;
        #pragma unroll
        for (int kk = 0; kk < 8; kk++) {
            uint32_t a[4];
            ldsm4(a, arbase + ((uint32_t)((2 * kk + hi) ^ ar7) << 4));
            #pragma unroll
            for (int jp = 0; jp < 4; jp++) {
                const int n0 = 64 * nw + 16 * jp;
                uint32_t bb[4];
                ldsm4(bb, sM1 + ((n0 + lsel) * M1STR + 16 * kk + lhi8) * 2);
                mma16816(accb[2 * jp],     a, bb[0], bb[2]);
                mma16816(accb[2 * jp + 1], a, bb[1], bb[3]);
            }
        }
        // scatter: rows (o1*16 + o2), cols (li0*8 + r1); li0 = mw
        #pragma unroll
        for (int j = 0; j < 8; j++) {
            const int o1 = 8 * nw + j;
            __half* p = &T1c[(16 * o1 + g) * T1STR + 8 * mw + 2 * c];
            *(half2*)p               = __floats2half2_rn(accb[j][0], accb[j][1]);
            *(half2*)(p + 8 * T1STR) = __floats2half2_rn(accb[j][2], accb[j][3]);
        }
    };

    // ---- stage C: T1 (256x32) @ M0^T chunk-k -> register accumulators ----
    auto stageC = [&](int t) {
        #pragma unroll
        for (int ks = 0; ks < 2; ks++) {
            uint32_t a[2][4];
            #pragma unroll
            for (int mi = 0; mi < 2; mi++) {
                const int mt = w + 8 * mi;
                ldsm4(a[mi], sT1 + ((16 * mt + lsel) * T1STR + 16 * ks + lhi8) * 2);
            }
            uint32_t bb[4];
            ldsm4(bb, sM0 + (lsel * M0STR + 32 * t + 16 * ks + lhi8) * 2);
            mma16816(accc[0][0], a[0], bb[0], bb[2]);
            mma16816(accc[0][1], a[0], bb[1], bb[3]);
            mma16816(accc[1][0], a[1], bb[0], bb[2]);
            mma16816(accc[1][1], a[1], bb[1], bb[3]);
        }
    };

    // ---- pipeline: A0 s [B s C,A+1 s] x4 ----
    stageA(0);
    __syncthreads();
    #pragma unroll
    for (int t = 0; t < 4; t++) {
        stageB();
        __syncthreads();
        stageC(t);
        if (t < 3) stageA(t + 1);
        __syncthreads();
    }

    // ---- epilogue: transpose through Ysm, then coalesced bias+store ----
    #pragma unroll
    for (int mi = 0; mi < 2; mi++) {
        const int row0 = 16 * (w + 8 * mi) + g;   // o1*16+o2
        #pragma unroll
        for (int nt = 0; nt < 2; nt++) {
            const int col0 = 8 * nt + 2 * c;      // o0
            Ysm[(col0)     * YSTR + row0]     = accc[mi][nt][0];
            Ysm[(col0 + 1) * YSTR + row0]     = accc[mi][nt][1];
            Ysm[(col0)     * YSTR + row0 + 8] = accc[mi][nt][2];
            Ysm[(col0 + 1) * YSTR + row0 + 8] = accc[mi][nt][3];
        }
    }
    __syncthreads();

    float* yr = y + (size_t)b * 4096;
    #pragma unroll
    for (int it = 0; it < 16; it++) {
        const int i = tid + 256 * it;             // i = o0*256 + row
        const int o0 = i >> 8, row = i & 255;
        yr[i] = Ysm[o0 * YSTR + row] + bias[i];
    }
}

extern "C" void kernel_launch(void* const* d_in, const int* in_sizes, int n_in,
                              void* d_out, int out_size) {
    const float* x    = (const float*)d_in[0];
    const float* c0   = (const float*)d_in[1];
    const float* c1   = (const float*)d_in[2];
    const float* c2   = (const float*)d_in[3];
    const float* bias = (const float*)d_in[4];
    float* y = (float*)d_out;

    cudaFuncSetAttribute(tt_linear_kernel,
                         cudaFuncAttributeMaxDynamicSharedMemorySize,
                         SMEM_BYTES);

    tt_prep_cores<<<32, 512>>>(c0, c1, c2);
    tt_linear_kernel<<<8192, 256, SMEM_BYTES>>>(x, bias, y);
}

// round 8
// speedup vs baseline: 1.1623x; 1.1623x over previous
#include <cuda_runtime.h>
#include <cuda_fp16.h>
#include <stdint.h>

// ---------------------------------------------------------------------------
// TT-linear fused kernel, v8.
// 2 i0-chunks (M=128 stage-B), stage B split into two N=64 passes (acc 32
// regs). All core-matrix operands pre-baked into fragment-ordered gmem arrays
// (L1-hot, no smem, no prologue). smem = swizzled T2 (32KB) + T1 (32KB)
// -> 3 CTAs/SM at 256 threads, regs target 84.
// ---------------------------------------------------------------------------

#define B_T2 0
#define B_T1 32768
#define SMEM_BYTES (65536 + 1024)   // +1024 manual-align slack

// fragment-ordered core matrices (fp16):
//  g_M1f[((kk*8+nt)*32+lane)*8 + r*2+h] = M1[16nt+g+8(r&1)][16kk+8(r>>1)+2c+h]
//     where M1[n=(o1*8+r1)][k=(i1*8+r2)] = core1[r1][o1][i1][r2]
//  g_M2f[(nt8*32+lane)*4 + r*2+h] = M2[8*nt8+g][8r+2c+h]
//     where M2[n=(o2*8+r2)][k] = core2[r2][o2][sigma(k)]
//  g_M0f[((ch*4+ks)*32+lane)*8 + r*2+h] = M0[g+8(r&1)][64ch+16ks+8(r>>1)+2c+h]
//     where M0[n=o0][k=(i0*8+r1)] = core0[o0][i0][r1]
__device__ __half g_M1f[8 * 8 * 32 * 8];   // 32KB
__device__ __half g_M2f[16 * 32 * 4];      // 4KB
__device__ __half g_M0f[2 * 4 * 32 * 8];   // 4KB

__global__ void tt_prep_cores(const float* __restrict__ c0,
                              const float* __restrict__ c1,
                              const float* __restrict__ c2) {
    int t = blockIdx.x * blockDim.x + threadIdx.x;
    int lane = t & 31, g = (lane >> 2), c = lane & 3;
    if (t < 2048) {                       // M1f: (kk, nt, lane)
        int kk = t >> 8, nt = (t >> 5) & 7;
        #pragma unroll
        for (int r = 0; r < 4; r++)
            #pragma unroll
            for (int h = 0; h < 2; h++) {
                int n = 16 * nt + g + 8 * (r & 1);
                int k = 16 * kk + 8 * (r >> 1) + 2 * c + h;
                int o1 = n >> 3, r1 = n & 7, i1 = k >> 3, r2 = k & 7;
                g_M1f[t * 8 + r * 2 + h] =
                    __float2half(c1[((r1 * 16 + o1) * 16 + i1) * 8 + r2]);
            }
    }
    if (t < 512) {                        // M2f: (nt8, lane)
        int nt8 = t >> 5;
        #pragma unroll
        for (int r = 0; r < 2; r++)
            #pragma unroll
            for (int h = 0; h < 2; h++) {
                int n = 8 * nt8 + g;
                int k = 8 * r + 2 * c + h;            // logical mma-k
                int o2 = n >> 3, r2 = n & 7;
                int cc = (k >> 1) & 3, d = k & 1, e = k >> 3;
                int i2 = 4 * cc + 2 * e + d;          // sigma(k)
                g_M2f[t * 4 + r * 2 + h] =
                    __float2half(c2[(r2 * 16 + o2) * 16 + i2]);
            }
    }
    if (t < 256) {                        // M0f: (ch, ks, lane)
        int ch = t >> 7, ks = (t >> 5) & 3;
        #pragma unroll
        for (int r = 0; r < 4; r++)
            #pragma unroll
            for (int h = 0; h < 2; h++) {
                int n = g + 8 * (r & 1);              // o0
                int k = 64 * ch + 16 * ks + 8 * (r >> 1) + 2 * c + h;
                int i0 = k >> 3, r1 = k & 7;
                g_M0f[t * 8 + r * 2 + h] =
                    __float2half(c0[(n * 16 + i0) * 8 + r1]);
            }
    }
}

__device__ __forceinline__ void mma16816(float* d, const uint32_t* a,
                                         uint32_t b0, uint32_t b1) {
    asm volatile(
        "mma.sync.aligned.m16n8k16.row.col.f32.f16.f16.f32 "
        "{%0,%1,%2,%3}, {%4,%5,%6,%7}, {%8,%9}, {%0,%1,%2,%3};\n"
        : "+f"(d[0]), "+f"(d[1]), "+f"(d[2]), "+f"(d[3])
        : "r"(a[0]), "r"(a[1]), "r"(a[2]), "r"(a[3]), "r"(b0), "r"(b1));
}

__device__ __forceinline__ void ldsm4(uint32_t* r, uint32_t addr) {
    asm volatile(
        "ldmatrix.sync.aligned.m8n8.x4.shared.b16 {%0,%1,%2,%3}, [%4];\n"
        : "=r"(r[0]), "=r"(r[1]), "=r"(r[2]), "=r"(r[3]) : "r"(addr));
}

__device__ __forceinline__ uint32_t packh2(float lo, float hi) {
    __half2 h = __floats2half2_rn(lo, hi);
    return *(uint32_t*)&h;
}

__global__ void __launch_bounds__(256, 3)
tt_linear_kernel(const float* __restrict__ x, const float* __restrict__ bias,
                 float* __restrict__ y) {
    extern __shared__ __half smem[];
    uint32_t sbase;
    asm("{ .reg .u64 t; cvta.to.shared.u64 t, %1; cvt.u32.u64 %0, t; }"
        : "=r"(sbase) : "l"(smem));
    const uint32_t abase = (sbase + 1023) & ~1023u;
    char* sc = (char*)smem + (abase - sbase);

    __half* T1c = (__half*)(sc + B_T1);
    float*  Ysm = (float*)(sc + B_T2);    // aliases T2 (dead at epilogue)

    const int b    = blockIdx.x;
    const int tid  = threadIdx.x;
    const int w    = tid >> 5;
    const int lane = tid & 31;
    const int g = lane >> 2, c = lane & 3;
    const int lsel = lane & 15;
    const int hi   = lane >> 4;            // ldsm k-chunk select

    const int mw = w & 3;                  // stage A/B m-warp
    const int nw = w >> 2;                 // stage A/B n-warp

    const uint32_t sT2 = abase + B_T2;
    const uint32_t sT1 = abase + B_T1;

    const float* xr = x + (size_t)b * 4096;
    const uint4* M1v = (const uint4*)g_M1f;
    const uint2* M2v = (const uint2*)g_M2f;
    const uint4* M0v = (const uint4*)g_M0f;

    float accc[2][2][4];
    #pragma unroll
    for (int mi = 0; mi < 2; mi++)
        #pragma unroll
        for (int nt = 0; nt < 2; nt++)
            #pragma unroll
            for (int q = 0; q < 4; q++) accc[mi][nt][q] = 0.f;

    // ---- stage A: x chunk (8 i0 rows) @ M2^T -> swizzled T2 ----
    // T2 row = li0*16 + o2 (256B rows, 16 chunks, XOR ^(row&7) on chunk)
    auto stageA = [&](int t) {
        uint32_t a[2][4];
        #pragma unroll
        for (int mi = 0; mi < 2; mi++) {
            const int li0 = 2 * mw + mi;
            const float* rp = xr + (8 * t + li0) * 256 + 16 * g + 4 * c;
            float4 f0 = *(const float4*)(rp);
            float4 f1 = *(const float4*)(rp + 128);
            a[mi][0] = packh2(f0.x, f0.y);
            a[mi][1] = packh2(f1.x, f1.y);
            a[mi][2] = packh2(f0.z, f0.w);
            a[mi][3] = packh2(f1.z, f1.w);
        }
        #pragma unroll
        for (int j = 0; j < 8; j++) {
            const int nt8 = 8 * nw + j;           // o2
            uint2 bf = M2v[nt8 * 32 + lane];
            #pragma unroll
            for (int mi = 0; mi < 2; mi++) {
                const int li0 = 2 * mw + mi;
                float d[4] = {0.f, 0.f, 0.f, 0.f};
                mma16816(d, a[mi], bf.x, bf.y);
                const int row = 16 * li0 + nt8;
                char* rowp = sc + B_T2 + row * 256 + 4 * c;
                const int sw = (g ^ (row & 7)) << 4;
                *(half2*)(rowp + sw)       = __floats2half2_rn(d[0], d[1]);
                *(half2*)(rowp + sw + 128) = __floats2half2_rn(d[2], d[3]);
            }
        }
    };

    // ---- stage B: T2 (128x128) @ M1^T, two N=64 passes -> scatter to T1 ----
    auto stageB = [&]() {
        #pragma unroll
        for (int p = 0; p < 2; p++) {
            float accb[2][2][2][4];
            #pragma unroll
            for (int mi = 0; mi < 2; mi++)
                #pragma unroll
                for (int jj = 0; jj < 2; jj++)
                    #pragma unroll
                    for (int s = 0; s < 2; s++)
                        #pragma unroll
                        for (int q = 0; q < 4; q++) accb[mi][jj][s][q] = 0.f;

            #pragma unroll
            for (int kk = 0; kk < 8; kk++) {
                uint32_t a[2][4];
                #pragma unroll
                for (int mi = 0; mi < 2; mi++) {
                    const int ar = 32 * mw + 16 * mi + lsel;
                    ldsm4(a[mi], sT2 + ar * 256 +
                                 ((uint32_t)((2 * kk + hi) ^ (ar & 7)) << 4));
                }
                #pragma unroll
                for (int jj = 0; jj < 2; jj++) {
                    const int nt = 4 * p + 2 * nw + jj;   // 16-wide n-tile
                    uint4 bf = M1v[(kk * 8 + nt) * 32 + lane];
                    #pragma unroll
                    for (int mi = 0; mi < 2; mi++) {
                        mma16816(accb[mi][jj][0], a[mi], bf.x, bf.z);
                        mma16816(accb[mi][jj][1], a[mi], bf.y, bf.w);
                    }
                }
            }
            // scatter to T1 (128B rows, XOR ^(row&7)=g on chunk li0)
            #pragma unroll
            for (int mi = 0; mi < 2; mi++) {
                const int li0 = 2 * mw + mi;
                const int swc = (li0 ^ g) << 4;
                #pragma unroll
                for (int jj = 0; jj < 2; jj++) {
                    const int nt = 4 * p + 2 * nw + jj;
                    #pragma unroll
                    for (int s = 0; s < 2; s++) {
                        const int o1 = 2 * nt + s;
                        char* p0 = sc + B_T1 + (16 * o1 + g) * 128 + swc + 4 * c;
                        *(half2*)p0 = __floats2half2_rn(accb[mi][jj][s][0],
                                                        accb[mi][jj][s][1]);
                        *(half2*)(p0 + 8 * 128) =
                            __floats2half2_rn(accb[mi][jj][s][2],
                                              accb[mi][jj][s][3]);
                    }
                }
            }
        }
    };

    // ---- stage C: T1 (256x64) @ M0^T chunk -> register accumulators ----
    auto stageC = [&](int ch) {
        #pragma unroll
        for (int ks = 0; ks < 4; ks++) {
            uint32_t a[2][4];
            #pragma unroll
            for (int mi = 0; mi < 2; mi++) {
                const int row = 16 * (w + 8 * mi) + lsel;
                ldsm4(a[mi], sT1 + row * 128 +
                             ((uint32_t)((2 * ks + hi) ^ (row & 7)) << 4));
            }
            uint4 bf = M0v[(ch * 4 + ks) * 32 + lane];
            #pragma unroll
            for (int mi = 0; mi < 2; mi++) {
                mma16816(accc[mi][0], a[mi], bf.x, bf.z);
                mma16816(accc[mi][1], a[mi], bf.y, bf.w);
            }
        }
    };

    // ---- pipeline ----
    stageA(0);
    __syncthreads();
    stageB();
    __syncthreads();
    stageC(0);
    stageA(1);
    __syncthreads();
    stageB();
    __syncthreads();
    stageC(1);

    // ---- epilogue: transpose through Ysm (stride 260), float4 out ----
    #pragma unroll
    for (int mi = 0; mi < 2; mi++) {
        const int row0 = 16 * (w + 8 * mi) + g;   // o1*16+o2
        #pragma unroll
        for (int nt = 0; nt < 2; nt++) {
            const int col0 = 8 * nt + 2 * c;      // o0
            Ysm[(col0)     * 260 + row0]     = accc[mi][nt][0];
            Ysm[(col0 + 1) * 260 + row0]     = accc[mi][nt][1];
            Ysm[(col0)     * 260 + row0 + 8] = accc[mi][nt][2];
            Ysm[(col0 + 1) * 260 + row0 + 8] = accc[mi][nt][3];
        }
    }
    __syncthreads();

    float* yr = y + (size_t)b * 4096;
    #pragma unroll
    for (int it = 0; it < 4; it++) {
        const int i = 4 * (tid + 256 * it);       // i = o0*256 + row
        const int o0 = i >> 8, row = i & 255;
        float4 v = *(const float4*)&Ysm[o0 * 260 + row];
        float4 bb = *(const float4*)&bias[i];
        v.x += bb.x; v.y += bb.y; v.z += bb.z; v.w += bb.w;
        *(float4*)&yr[i] = v;
    }
}

extern "C" void kernel_launch(void* const* d_in, const int* in_sizes, int n_in,
                              void* d_out, int out_size) {
    const float* x    = (const float*)d_in[0];
    const float* c0   = (const float*)d_in[1];
    const float* c1   = (const float*)d_in[2];
    const float* c2   = (const float*)d_in[3];
    const float* bias = (const float*)d_in[4];
    float* y = (float*)d_out;

    cudaFuncSetAttribute(tt_linear_kernel,
                         cudaFuncAttributeMaxDynamicSharedMemorySize,
                         SMEM_BYTES);

    tt_prep_cores<<<4, 512>>>(c0, c1, c2);
    tt_linear_kernel<<<8192, 256, SMEM_BYTES>>>(x, bias, y);
}

// round 9
// speedup vs baseline: 1.2555x; 1.0802x over previous
#include <cuda_runtime.h>
#include <cuda_fp16.h>
#include <stdint.h>

// ---------------------------------------------------------------------------
// TT-linear fused kernel, v9 = v8 + fp16 accumulators in stages A/B
// (single-pass stage B, halved A-ldsm traffic) + stmatrix T1 stores.
// 2 i0-chunks (M=128 stage-B). Core operands fragment-ordered in gmem.
// smem = swizzled T2 (32KB) + T1 (32KB) -> 3 CTAs/SM.
// ---------------------------------------------------------------------------

#define B_T2 0
#define B_T1 32768
#define SMEM_BYTES (65536 + 1024)   // +1024 manual-align slack

// fragment-ordered core matrices (fp16): same layouts as v8 (passing)
__device__ __half g_M1f[8 * 8 * 32 * 8];   // 32KB
__device__ __half g_M2f[16 * 32 * 4];      // 4KB
__device__ __half g_M0f[2 * 4 * 32 * 8];   // 4KB

__global__ void tt_prep_cores(const float* __restrict__ c0,
                              const float* __restrict__ c1,
                              const float* __restrict__ c2) {
    int t = blockIdx.x * blockDim.x + threadIdx.x;
    int lane = t & 31, g = (lane >> 2), c = lane & 3;
    if (t < 2048) {                       // M1f: (kk, nt, lane)
        int kk = t >> 8, nt = (t >> 5) & 7;
        #pragma unroll
        for (int r = 0; r < 4; r++)
            #pragma unroll
            for (int h = 0; h < 2; h++) {
                int n = 16 * nt + g + 8 * (r & 1);
                int k = 16 * kk + 8 * (r >> 1) + 2 * c + h;
                int o1 = n >> 3, r1 = n & 7, i1 = k >> 3, r2 = k & 7;
                g_M1f[t * 8 + r * 2 + h] =
                    __float2half(c1[((r1 * 16 + o1) * 16 + i1) * 8 + r2]);
            }
    }
    if (t < 512) {                        // M2f: (nt8, lane)
        int nt8 = t >> 5;
        #pragma unroll
        for (int r = 0; r < 2; r++)
            #pragma unroll
            for (int h = 0; h < 2; h++) {
                int n = 8 * nt8 + g;
                int k = 8 * r + 2 * c + h;            // logical mma-k
                int o2 = n >> 3, r2 = n & 7;
                int cc = (k >> 1) & 3, d = k & 1, e = k >> 3;
                int i2 = 4 * cc + 2 * e + d;          // sigma(k)
                g_M2f[t * 4 + r * 2 + h] =
                    __float2half(c2[(r2 * 16 + o2) * 16 + i2]);
            }
    }
    if (t < 256) {                        // M0f: (ch, ks, lane)
        int ch = t >> 7, ks = (t >> 5) & 3;
        #pragma unroll
        for (int r = 0; r < 4; r++)
            #pragma unroll
            for (int h = 0; h < 2; h++) {
                int n = g + 8 * (r & 1);              // o0
                int k = 64 * ch + 16 * ks + 8 * (r >> 1) + 2 * c + h;
                int i0 = k >> 3, r1 = k & 7;
                g_M0f[t * 8 + r * 2 + h] =
                    __float2half(c0[(n * 16 + i0) * 8 + r1]);
            }
    }
}

__device__ __forceinline__ void mma16816(float* d, const uint32_t* a,
                                         uint32_t b0, uint32_t b1) {
    asm volatile(
        "mma.sync.aligned.m16n8k16.row.col.f32.f16.f16.f32 "
        "{%0,%1,%2,%3}, {%4,%5,%6,%7}, {%8,%9}, {%0,%1,%2,%3};\n"
        : "+f"(d[0]), "+f"(d[1]), "+f"(d[2]), "+f"(d[3])
        : "r"(a[0]), "r"(a[1]), "r"(a[2]), "r"(a[3]), "r"(b0), "r"(b1));
}

// fp16-accumulator mma: D,C are 2x .f16x2 regs
__device__ __forceinline__ void mma16816h(uint32_t* d, const uint32_t* a,
                                          uint32_t b0, uint32_t b1) {
    asm volatile(
        "mma.sync.aligned.m16n8k16.row.col.f16.f16.f16.f16 "
        "{%0,%1}, {%2,%3,%4,%5}, {%6,%7}, {%0,%1};\n"
        : "+r"(d[0]), "+r"(d[1])
        : "r"(a[0]), "r"(a[1]), "r"(a[2]), "r"(a[3]), "r"(b0), "r"(b1));
}

__device__ __forceinline__ void ldsm4(uint32_t* r, uint32_t addr) {
    asm volatile(
        "ldmatrix.sync.aligned.m8n8.x4.shared.b16 {%0,%1,%2,%3}, [%4];\n"
        : "=r"(r[0]), "=r"(r[1]), "=r"(r[2]), "=r"(r[3]) : "r"(addr));
}

__device__ __forceinline__ void stsm4(uint32_t addr, uint32_t r0, uint32_t r1,
                                      uint32_t r2, uint32_t r3) {
    asm volatile(
        "stmatrix.sync.aligned.m8n8.x4.shared.b16 [%0], {%1,%2,%3,%4};\n"
        :: "r"(addr), "r"(r0), "r"(r1), "r"(r2), "r"(r3) : "memory");
}

__device__ __forceinline__ uint32_t packh2(float lo, float hi) {
    __half2 h = __floats2half2_rn(lo, hi);
    return *(uint32_t*)&h;
}

__global__ void __launch_bounds__(256, 3)
tt_linear_kernel(const float* __restrict__ x, const float* __restrict__ bias,
                 float* __restrict__ y) {
    extern __shared__ __half smem[];
    uint32_t sbase;
    asm("{ .reg .u64 t; cvta.to.shared.u64 t, %1; cvt.u32.u64 %0, t; }"
        : "=r"(sbase) : "l"(smem));
    const uint32_t abase = (sbase + 1023) & ~1023u;
    char* sc = (char*)smem + (abase - sbase);

    float* Ysm = (float*)(sc + B_T2);     // aliases T2 (dead at epilogue)

    const int b    = blockIdx.x;
    const int tid  = threadIdx.x;
    const int w    = tid >> 5;
    const int lane = tid & 31;
    const int g = lane >> 2, c = lane & 3;
    const int lsel = lane & 15;
    const int hi   = lane >> 4;            // ldsm k-chunk select

    const int mw = w & 3;                  // stage A/B m-warp
    const int nw = w >> 2;                 // stage A/B n-warp

    const uint32_t sT2 = abase + B_T2;
    const uint32_t sT1 = abase + B_T1;

    const float* xr = x + (size_t)b * 4096;
    const uint4* M1v = (const uint4*)g_M1f;
    const uint2* M2v = (const uint2*)g_M2f;
    const uint4* M0v = (const uint4*)g_M0f;

    float accc[2][2][4];
    #pragma unroll
    for (int mi = 0; mi < 2; mi++)
        #pragma unroll
        for (int nt = 0; nt < 2; nt++)
            #pragma unroll
            for (int q = 0; q < 4; q++) accc[mi][nt][q] = 0.f;

    // ---- stage A: x chunk (8 i0 rows) @ M2^T -> swizzled T2 (f16 acc) ----
    auto stageA = [&](int t) {
        uint32_t a[2][4];
        #pragma unroll
        for (int mi = 0; mi < 2; mi++) {
            const int li0 = 2 * mw + mi;
            const float* rp = xr + (8 * t + li0) * 256 + 16 * g + 4 * c;
            float4 f0 = *(const float4*)(rp);
            float4 f1 = *(const float4*)(rp + 128);
            a[mi][0] = packh2(f0.x, f0.y);
            a[mi][1] = packh2(f1.x, f1.y);
            a[mi][2] = packh2(f0.z, f0.w);
            a[mi][3] = packh2(f1.z, f1.w);
        }
        #pragma unroll
        for (int j = 0; j < 8; j++) {
            const int nt8 = 8 * nw + j;           // o2
            uint2 bf = M2v[nt8 * 32 + lane];
            #pragma unroll
            for (int mi = 0; mi < 2; mi++) {
                uint32_t d[2] = {0u, 0u};
                mma16816h(d, a[mi], bf.x, bf.y);
                const int row = 16 * (2 * mw + mi) + nt8;
                char* rowp = sc + B_T2 + row * 256 + 4 * c;
                const int sw = (g ^ (row & 7)) << 4;
                *(uint32_t*)(rowp + sw)       = d[0];
                *(uint32_t*)(rowp + sw + 128) = d[1];
            }
        }
    };

    // ---- stage B: T2 (128x128) @ M1^T, ONE pass (f16 acc, 32 regs),
    //      stmatrix scatter to T1 ----
    auto stageB = [&]() {
        uint32_t accb[2][8][2];
        #pragma unroll
        for (int mi = 0; mi < 2; mi++)
            #pragma unroll
            for (int s = 0; s < 8; s++) {
                accb[mi][s][0] = 0u;
                accb[mi][s][1] = 0u;
            }

        #pragma unroll
        for (int kk = 0; kk < 8; kk++) {
            uint32_t a[2][4];
            #pragma unroll
            for (int mi = 0; mi < 2; mi++) {
                const int ar = 32 * mw + 16 * mi + lsel;
                ldsm4(a[mi], sT2 + ar * 256 +
                             ((uint32_t)((2 * kk + hi) ^ (ar & 7)) << 4));
            }
            #pragma unroll
            for (int jj = 0; jj < 4; jj++) {
                const int nt = 4 * nw + jj;           // 16-wide n-tile
                uint4 bf = M1v[(kk * 8 + nt) * 32 + lane];
                #pragma unroll
                for (int mi = 0; mi < 2; mi++) {
                    mma16816h(accb[mi][2 * jj],     a[mi], bf.x, bf.z);
                    mma16816h(accb[mi][2 * jj + 1], a[mi], bf.y, bf.w);
                }
            }
        }
        // stmatrix: matrices (mi, rowhalf) per o1-slot; T1 row (16*o1+o2),
        // col-chunk li0 with XOR ^(row&7) swizzle.
        const int msel = lane >> 3;            // matrix id 0..3
        const int o2r  = lane & 7;
        const int mi_s = msel >> 1;
        const int dlt  = msel & 1;
        const uint32_t rowoff =
            (uint32_t)(o2r + 8 * dlt) * 128 +
            ((uint32_t)((2 * mw + mi_s) ^ o2r) << 4);
        #pragma unroll
        for (int slot = 0; slot < 8; slot++) {
            const int o1 = 8 * nw + slot;          // = 2*nt + s
            stsm4(sT1 + (uint32_t)(16 * o1) * 128 + rowoff,
                  accb[0][slot][0], accb[0][slot][1],
                  accb[1][slot][0], accb[1][slot][1]);
        }
    };

    // ---- stage C: T1 (256x64) @ M0^T chunk -> fp32 register accumulators ----
    auto stageC = [&](int ch) {
        #pragma unroll
        for (int ks = 0; ks < 4; ks++) {
            uint32_t a[2][4];
            #pragma unroll
            for (int mi = 0; mi < 2; mi++) {
                const int row = 16 * (w + 8 * mi) + lsel;
                ldsm4(a[mi], sT1 + row * 128 +
                             ((uint32_t)((2 * ks + hi) ^ (row & 7)) << 4));
            }
            uint4 bf = M0v[(ch * 4 + ks) * 32 + lane];
            #pragma unroll
            for (int mi = 0; mi < 2; mi++) {
                mma16816(accc[mi][0], a[mi], bf.x, bf.z);
                mma16816(accc[mi][1], a[mi], bf.y, bf.w);
            }
        }
    };

    // ---- pipeline ----
    stageA(0);
    __syncthreads();
    stageB();
    __syncthreads();
    stageC(0);
    stageA(1);
    __syncthreads();
    stageB();
    __syncthreads();
    stageC(1);

    // ---- epilogue: transpose through Ysm (stride 260), float4 out ----
    #pragma unroll
    for (int mi = 0; mi < 2; mi++) {
        const int row0 = 16 * (w + 8 * mi) + g;   // o1*16+o2
        #pragma unroll
        for (int nt = 0; nt < 2; nt++) {
            const int col0 = 8 * nt + 2 * c;      // o0
            Ysm[(col0)     * 260 + row0]     = accc[mi][nt][0];
            Ysm[(col0 + 1) * 260 + row0]     = accc[mi][nt][1];
            Ysm[(col0)     * 260 + row0 + 8] = accc[mi][nt][2];
            Ysm[(col0 + 1) * 260 + row0 + 8] = accc[mi][nt][3];
        }
    }
    __syncthreads();

    float* yr = y + (size_t)b * 4096;
    #pragma unroll
    for (int it = 0; it < 4; it++) {
        const int i = 4 * (tid + 256 * it);       // i = o0*256 + row
        const int o0 = i >> 8, row = i & 255;
        float4 v = *(const float4*)&Ysm[o0 * 260 + row];
        float4 bb = *(const float4*)&bias[i];
        v.x += bb.x; v.y += bb.y; v.z += bb.z; v.w += bb.w;
        *(float4*)&yr[i] = v;
    }
}

extern "C" void kernel_launch(void* const* d_in, const int* in_sizes, int n_in,
                              void* d_out, int out_size) {
    const float* x    = (const float*)d_in[0];
    const float* c0   = (const float*)d_in[1];
    const float* c1   = (const float*)d_in[2];
    const float* c2   = (const float*)d_in[3];
    const float* bias = (const float*)d_in[4];
    float* y = (float*)d_out;

    cudaFuncSetAttribute(tt_linear_kernel,
                         cudaFuncAttributeMaxDynamicSharedMemorySize,
                         SMEM_BYTES);

    tt_prep_cores<<<4, 512>>>(c0, c1, c2);
    tt_linear_kernel<<<8192, 256, SMEM_BYTES>>>(x, bias, y);
}

// round 10
// speedup vs baseline: 1.3782x; 1.0977x over previous
#include <cuda_runtime.h>
#include <cuda_fp16.h>
#include <stdint.h>

// ---------------------------------------------------------------------------
// TT-linear fused kernel, v10: single-pass M=256 stage B (f16 acc, 64 regs),
// T1 aliased onto T2 (one 64KB smem buffer; stage B holds results in regs
// across a sync). stmatrix for stage-A and stage-B scatters. 2 CTAs/SM.
// ---------------------------------------------------------------------------

#define SMEM_BYTES (65536 + 1024)

// fragment-ordered core matrices (fp16), same layouts as v8/v9 (passing):
__device__ __half g_M1f[8 * 8 * 32 * 8];   // 32KB
__device__ __half g_M2f[16 * 32 * 4];      // 4KB
__device__ __half g_M0f[2 * 4 * 32 * 8];   // 4KB

__global__ void tt_prep_cores(const float* __restrict__ c0,
                              const float* __restrict__ c1,
                              const float* __restrict__ c2) {
    int t = blockIdx.x * blockDim.x + threadIdx.x;
    int lane = t & 31, g = (lane >> 2), c = lane & 3;
    if (t < 2048) {                       // M1f: (kk, nt, lane)
        int kk = t >> 8, nt = (t >> 5) & 7;
        #pragma unroll
        for (int r = 0; r < 4; r++)
            #pragma unroll
            for (int h = 0; h < 2; h++) {
                int n = 16 * nt + g + 8 * (r & 1);
                int k = 16 * kk + 8 * (r >> 1) + 2 * c + h;
                int o1 = n >> 3, r1 = n & 7, i1 = k >> 3, r2 = k & 7;
                g_M1f[t * 8 + r * 2 + h] =
                    __float2half(c1[((r1 * 16 + o1) * 16 + i1) * 8 + r2]);
            }
    }
    if (t < 512) {                        // M2f: (nt8, lane)
        int nt8 = t >> 5;
        #pragma unroll
        for (int r = 0; r < 2; r++)
            #pragma unroll
            for (int h = 0; h < 2; h++) {
                int n = 8 * nt8 + g;
                int k = 8 * r + 2 * c + h;            // logical mma-k
                int o2 = n >> 3, r2 = n & 7;
                int cc = (k >> 1) & 3, d = k & 1, e = k >> 3;
                int i2 = 4 * cc + 2 * e + d;          // sigma(k)
                g_M2f[t * 4 + r * 2 + h] =
                    __float2half(c2[(r2 * 16 + o2) * 16 + i2]);
            }
    }
    if (t < 256) {                        // M0f: (ks'=0..7, lane)
        int ks = t >> 5;                  // global 16-k step
        #pragma unroll
        for (int r = 0; r < 4; r++)
            #pragma unroll
            for (int h = 0; h < 2; h++) {
                int n = g + 8 * (r & 1);              // o0
                int k = 16 * ks + 8 * (r >> 1) + 2 * c + h;
                int i0 = k >> 3, r1 = k & 7;
                g_M0f[t * 8 + r * 2 + h] =
                    __float2half(c0[(n * 16 + i0) * 8 + r1]);
            }
    }
}

__device__ __forceinline__ void mma16816(float* d, const uint32_t* a,
                                         uint32_t b0, uint32_t b1) {
    asm volatile(
        "mma.sync.aligned.m16n8k16.row.col.f32.f16.f16.f32 "
        "{%0,%1,%2,%3}, {%4,%5,%6,%7}, {%8,%9}, {%0,%1,%2,%3};\n"
        : "+f"(d[0]), "+f"(d[1]), "+f"(d[2]), "+f"(d[3])
        : "r"(a[0]), "r"(a[1]), "r"(a[2]), "r"(a[3]), "r"(b0), "r"(b1));
}

__device__ __forceinline__ void mma16816h(uint32_t* d, const uint32_t* a,
                                          uint32_t b0, uint32_t b1) {
    asm volatile(
        "mma.sync.aligned.m16n8k16.row.col.f16.f16.f16.f16 "
        "{%0,%1}, {%2,%3,%4,%5}, {%6,%7}, {%0,%1};\n"
        : "+r"(d[0]), "+r"(d[1])
        : "r"(a[0]), "r"(a[1]), "r"(a[2]), "r"(a[3]), "r"(b0), "r"(b1));
}

__device__ __forceinline__ void ldsm4(uint32_t* r, uint32_t addr) {
    asm volatile(
        "ldmatrix.sync.aligned.m8n8.x4.shared.b16 {%0,%1,%2,%3}, [%4];\n"
        : "=r"(r[0]), "=r"(r[1]), "=r"(r[2]), "=r"(r[3]) : "r"(addr));
}

__device__ __forceinline__ void stsm4(uint32_t addr, uint32_t r0, uint32_t r1,
                                      uint32_t r2, uint32_t r3) {
    asm volatile(
        "stmatrix.sync.aligned.m8n8.x4.shared.b16 [%0], {%1,%2,%3,%4};\n"
        :: "r"(addr), "r"(r0), "r"(r1), "r"(r2), "r"(r3) : "memory");
}

__device__ __forceinline__ uint32_t packh2(float lo, float hi) {
    __half2 h = __floats2half2_rn(lo, hi);
    return *(uint32_t*)&h;
}

__global__ void __launch_bounds__(256, 2)
tt_linear_kernel(const float* __restrict__ x, const float* __restrict__ bias,
                 float* __restrict__ y) {
    extern __shared__ __half smem[];
    uint32_t sbase;
    asm("{ .reg .u64 t; cvta.to.shared.u64 t, %1; cvt.u32.u64 %0, t; }"
        : "=r"(sbase) : "l"(smem));
    const uint32_t abase = (sbase + 1023) & ~1023u;
    char* sc = (char*)smem + (abase - sbase);
    float* Ysm = (float*)sc;              // aliases BUF at epilogue

    const int b    = blockIdx.x;
    const int tid  = threadIdx.x;
    const int w    = tid >> 5;
    const int lane = tid & 31;
    const int g = lane >> 2, c = lane & 3;
    const int lsel = lane & 15;
    const int hi   = lane >> 4;
    const int msel = lane >> 3;            // stmatrix matrix id
    const int mrow = lane & 7;             // stmatrix row-in-matrix

    const int mw = w & 3;                  // stage A/B m-warp
    const int nw = w >> 2;                 // stage A/B n-warp

    const float* xr = x + (size_t)b * 4096;
    const uint4* M1v = (const uint4*)g_M1f;
    const uint2* M2v = (const uint2*)g_M2f;
    const uint4* M0v = (const uint4*)g_M0f;

    // =====================================================================
    // stage A: x (256 x 16 logical) @ M2^T -> BUF as T2
    // T2: row = i0*16 + o2 (256 rows x 256B), chunk = i1 (16x16B, XOR ^(row&7)
    // on low 3 bits). warp grid 4M x 2N; per warp 4 mi (i0 = 4mw+mi).
    // =====================================================================
    {
        uint32_t a[4][4];
        #pragma unroll
        for (int mi = 0; mi < 4; mi++) {
            const int li0 = 4 * mw + mi;
            const float* rp = xr + li0 * 256 + 16 * g + 4 * c;
            float4 f0 = *(const float4*)(rp);
            float4 f1 = *(const float4*)(rp + 128);
            a[mi][0] = packh2(f0.x, f0.y);
            a[mi][1] = packh2(f1.x, f1.y);
            a[mi][2] = packh2(f0.z, f0.w);
            a[mi][3] = packh2(f1.z, f1.w);
        }
        #pragma unroll
        for (int j = 0; j < 8; j++) {
            const int nt8 = 8 * nw + j;           // o2
            uint2 bf = M2v[nt8 * 32 + lane];
            uint32_t d[4][2];
            #pragma unroll
            for (int mi = 0; mi < 4; mi++) {
                d[mi][0] = 0u; d[mi][1] = 0u;
                mma16816h(d[mi], a[mi], bf.x, bf.y);
            }
            const int i1 = mrow + 8 * (msel & 1);
            const uint32_t swo = ((uint32_t)(i1 ^ (nt8 & 7))) << 4;
            #pragma unroll
            for (int p = 0; p < 2; p++) {
                const int li0 = 4 * mw + 2 * p + (msel >> 1);
                stsm4(abase + (uint32_t)(16 * li0 + nt8) * 256 + swo,
                      d[2 * p][0], d[2 * p][1], d[2 * p + 1][0], d[2 * p + 1][1]);
            }
        }
    }
    __syncthreads();

    // =====================================================================
    // stage B: T2 (256x128) @ M1^T, single pass, f16 acc (64 regs).
    // warp grid 4M x 2N: per warp 4 mi (64 m-rows), 4 jj (64 n-cols).
    // =====================================================================
    uint32_t accb[4][8][2];
    #pragma unroll
    for (int mi = 0; mi < 4; mi++)
        #pragma unroll
        for (int s = 0; s < 8; s++) {
            accb[mi][s][0] = 0u; accb[mi][s][1] = 0u;
        }
    #pragma unroll
    for (int kk = 0; kk < 8; kk++) {
        uint32_t a[4][4];
        #pragma unroll
        for (int mi = 0; mi < 4; mi++) {
            const int ar = 64 * mw + 16 * mi + lsel;
            ldsm4(a[mi], abase + (uint32_t)ar * 256 +
                         ((uint32_t)((2 * kk + hi) ^ (ar & 7)) << 4));
        }
        #pragma unroll
        for (int jj = 0; jj < 4; jj++) {
            const int nt = 4 * nw + jj;           // 16-wide n-tile
            uint4 bf = M1v[(kk * 8 + nt) * 32 + lane];
            #pragma unroll
            for (int mi = 0; mi < 4; mi++) {
                mma16816h(accb[mi][2 * jj],     a[mi], bf.x, bf.z);
                mma16816h(accb[mi][2 * jj + 1], a[mi], bf.y, bf.w);
            }
        }
    }
    __syncthreads();   // all T2 reads done; BUF is now reusable as T1

    // scatter to T1 (aliased): row = 16*o1 + o2 (256 rows x 256B),
    // chunk = i0 (16x16B, XOR ^(o2&7) on low 3 bits).
    {
        const int o2v = mrow + 8 * (msel & 1);
        #pragma unroll
        for (int p = 0; p < 2; p++) {
            const int c16 = 4 * mw + 2 * p + (msel >> 1);   // i0
            const uint32_t swo = ((uint32_t)(c16 ^ mrow)) << 4;
            #pragma unroll
            for (int slot = 0; slot < 8; slot++) {
                const int o1 = 8 * nw + slot;
                stsm4(abase + (uint32_t)(16 * o1 + o2v) * 256 + swo,
                      accb[2 * p][slot][0],     accb[2 * p][slot][1],
                      accb[2 * p + 1][slot][0], accb[2 * p + 1][slot][1]);
            }
        }
    }
    __syncthreads();

    // =====================================================================
    // stage C: T1 (256x128) @ M0^T -> fp32 register accumulators
    // =====================================================================
    float accc[2][2][4];
    #pragma unroll
    for (int mi = 0; mi < 2; mi++)
        #pragma unroll
        for (int nt = 0; nt < 2; nt++)
            #pragma unroll
            for (int q = 0; q < 4; q++) accc[mi][nt][q] = 0.f;

    #pragma unroll
    for (int ks = 0; ks < 8; ks++) {
        uint32_t a[2][4];
        #pragma unroll
        for (int mi = 0; mi < 2; mi++) {
            const int row = 16 * (w + 8 * mi) + lsel;
            ldsm4(a[mi], abase + (uint32_t)row * 256 +
                         ((uint32_t)((2 * ks + hi) ^ (lsel & 7)) << 4));
        }
        uint4 bf = M0v[ks * 32 + lane];
        #pragma unroll
        for (int mi = 0; mi < 2; mi++) {
            mma16816(accc[mi][0], a[mi], bf.x, bf.z);
            mma16816(accc[mi][1], a[mi], bf.y, bf.w);
        }
    }
    __syncthreads();   // T1 reads done; BUF reusable as Ysm

    // ---- epilogue: transpose through Ysm (stride 260), float4 out ----
    #pragma unroll
    for (int mi = 0; mi < 2; mi++) {
        const int row0 = 16 * (w + 8 * mi) + g;   // o1*16+o2
        #pragma unroll
        for (int nt = 0; nt < 2; nt++) {
            const int col0 = 8 * nt + 2 * c;      // o0
            Ysm[(col0)     * 260 + row0]     = accc[mi][nt][0];
            Ysm[(col0 + 1) * 260 + row0]     = accc[mi][nt][1];
            Ysm[(col0)     * 260 + row0 + 8] = accc[mi][nt][2];
            Ysm[(col0 + 1) * 260 + row0 + 8] = accc[mi][nt][3];
        }
    }
    __syncthreads();

    float* yr = y + (size_t)b * 4096;
    #pragma unroll
    for (int it = 0; it < 4; it++) {
        const int i = 4 * (tid + 256 * it);       // i = o0*256 + row
        const int o0 = i >> 8, row = i & 255;
        float4 v = *(const float4*)&Ysm[o0 * 260 + row];
        float4 bb = *(const float4*)&bias[i];
        v.x += bb.x; v.y += bb.y; v.z += bb.z; v.w += bb.w;
        *(float4*)&yr[i] = v;
    }
}

extern "C" void kernel_launch(void* const* d_in, const int* in_sizes, int n_in,
                              void* d_out, int out_size) {
    const float* x    = (const float*)d_in[0];
    const float* c0   = (const float*)d_in[1];
    const float* c1   = (const float*)d_in[2];
    const float* c2   = (const float*)d_in[3];
    const float* bias = (const float*)d_in[4];
    float* y = (float*)d_out;

    cudaFuncSetAttribute(tt_linear_kernel,
                         cudaFuncAttributeMaxDynamicSharedMemorySize,
                         SMEM_BYTES);

    tt_prep_cores<<<4, 512>>>(c0, c1, c2);
    tt_linear_kernel<<<8192, 256, SMEM_BYTES>>>(x, bias, y);
}

// round 11
// speedup vs baseline: 1.4012x; 1.0167x over previous
#include <cuda_runtime.h>
#include <cuda_fp16.h>
#include <stdint.h>

// ---------------------------------------------------------------------------
// TT-linear fused kernel, v11 = v10 + (a) stage-A 8M warp grid (x loaded once,
// no duplication), (b) f16 accumulators in stage C, (c) simplified swizzle
// address algebra. Single-pass M=256 stage B (f16 acc), one aliased 64KB
// smem buffer, 2 CTAs/SM.
// ---------------------------------------------------------------------------

#define SMEM_BYTES (65536 + 1024)

// fragment-ordered core matrices (fp16), layouts as v10 (passing):
__device__ __half g_M1f[8 * 8 * 32 * 8];   // 32KB
__device__ __half g_M2f[16 * 32 * 4];      // 4KB
__device__ __half g_M0f[8 * 32 * 8];       // 4KB

__global__ void tt_prep_cores(const float* __restrict__ c0,
                              const float* __restrict__ c1,
                              const float* __restrict__ c2) {
    int t = blockIdx.x * blockDim.x + threadIdx.x;
    int lane = t & 31, g = (lane >> 2), c = lane & 3;
    if (t < 2048) {                       // M1f: (kk, nt, lane)
        int kk = t >> 8, nt = (t >> 5) & 7;
        #pragma unroll
        for (int r = 0; r < 4; r++)
            #pragma unroll
            for (int h = 0; h < 2; h++) {
                int n = 16 * nt + g + 8 * (r & 1);
                int k = 16 * kk + 8 * (r >> 1) + 2 * c + h;
                int o1 = n >> 3, r1 = n & 7, i1 = k >> 3, r2 = k & 7;
                g_M1f[t * 8 + r * 2 + h] =
                    __float2half(c1[((r1 * 16 + o1) * 16 + i1) * 8 + r2]);
            }
    }
    if (t < 512) {                        // M2f: (nt8, lane)
        int nt8 = t >> 5;
        #pragma unroll
        for (int r = 0; r < 2; r++)
            #pragma unroll
            for (int h = 0; h < 2; h++) {
                int n = 8 * nt8 + g;
                int k = 8 * r + 2 * c + h;            // logical mma-k
                int o2 = n >> 3, r2 = n & 7;
                int cc = (k >> 1) & 3, d = k & 1, e = k >> 3;
                int i2 = 4 * cc + 2 * e + d;          // sigma(k)
                g_M2f[t * 4 + r * 2 + h] =
                    __float2half(c2[(r2 * 16 + o2) * 16 + i2]);
            }
    }
    if (t < 256) {                        // M0f: (ks=0..7, lane)
        int ks = t >> 5;
        #pragma unroll
        for (int r = 0; r < 4; r++)
            #pragma unroll
            for (int h = 0; h < 2; h++) {
                int n = g + 8 * (r & 1);              // o0
                int k = 16 * ks + 8 * (r >> 1) + 2 * c + h;
                int i0 = k >> 3, r1 = k & 7;
                g_M0f[t * 8 + r * 2 + h] =
                    __float2half(c0[(n * 16 + i0) * 8 + r1]);
            }
    }
}

__device__ __forceinline__ void mma16816h(uint32_t* d, const uint32_t* a,
                                          uint32_t b0, uint32_t b1) {
    asm volatile(
        "mma.sync.aligned.m16n8k16.row.col.f16.f16.f16.f16 "
        "{%0,%1}, {%2,%3,%4,%5}, {%6,%7}, {%0,%1};\n"
        : "+r"(d[0]), "+r"(d[1])
        : "r"(a[0]), "r"(a[1]), "r"(a[2]), "r"(a[3]), "r"(b0), "r"(b1));
}

__device__ __forceinline__ void ldsm4(uint32_t* r, uint32_t addr) {
    asm volatile(
        "ldmatrix.sync.aligned.m8n8.x4.shared.b16 {%0,%1,%2,%3}, [%4];\n"
        : "=r"(r[0]), "=r"(r[1]), "=r"(r[2]), "=r"(r[3]) : "r"(addr));
}

__device__ __forceinline__ void stsm4(uint32_t addr, uint32_t r0, uint32_t r1,
                                      uint32_t r2, uint32_t r3) {
    asm volatile(
        "stmatrix.sync.aligned.m8n8.x4.shared.b16 [%0], {%1,%2,%3,%4};\n"
        :: "r"(addr), "r"(r0), "r"(r1), "r"(r2), "r"(r3) : "memory");
}

__device__ __forceinline__ uint32_t packh2(float lo, float hi) {
    __half2 h = __floats2half2_rn(lo, hi);
    return *(uint32_t*)&h;
}

__global__ void __launch_bounds__(256, 2)
tt_linear_kernel(const float* __restrict__ x, const float* __restrict__ bias,
                 float* __restrict__ y) {
    extern __shared__ __half smem[];
    uint32_t sbase;
    asm("{ .reg .u64 t; cvta.to.shared.u64 t, %1; cvt.u32.u64 %0, t; }"
        : "=r"(sbase) : "l"(smem));
    const uint32_t abase = (sbase + 1023) & ~1023u;
    char* sc = (char*)smem + (abase - sbase);
    float* Ysm = (float*)sc;              // aliases BUF at epilogue

    const int b    = blockIdx.x;
    const int tid  = threadIdx.x;
    const int w    = tid >> 5;
    const int lane = tid & 31;
    const int g = lane >> 2, c = lane & 3;
    const int lsel = lane & 15;
    const int hi   = lane >> 4;
    const int msel = lane >> 3;            // stmatrix matrix id
    const int mrow = lane & 7;             // stmatrix row-in-matrix

    const int mw = w & 3;                  // stage B m-warp
    const int nw = w >> 2;                 // stage B n-warp

    const float* xr = x + (size_t)b * 4096;
    const uint4* M1v = (const uint4*)g_M1f;
    const uint2* M2v = (const uint2*)g_M2f;
    const uint4* M0v = (const uint4*)g_M0f;

    // =====================================================================
    // stage A: x (256x16 logical) @ M2^T -> BUF as T2.
    // 8M warp grid: warp w owns i0 in {2w, 2w+1} -> x loaded exactly once.
    // T2: row = i0*16 + o2 (256 rows x 256B), chunk = i1, XOR ^(row&7).
    // =====================================================================
    {
        uint32_t a[2][4];
        #pragma unroll
        for (int mi = 0; mi < 2; mi++) {
            const int li0 = 2 * w + mi;
            const float* rp = xr + li0 * 256 + 16 * g + 4 * c;
            float4 f0 = *(const float4*)(rp);
            float4 f1 = *(const float4*)(rp + 128);
            a[mi][0] = packh2(f0.x, f0.y);
            a[mi][1] = packh2(f1.x, f1.y);
            a[mi][2] = packh2(f0.z, f0.w);
            a[mi][3] = packh2(f1.z, f1.w);
        }
        const int i1s = mrow + 8 * (msel & 1);        // stsm source row
        const int li0s = 2 * w + (msel >> 1);
        #pragma unroll
        for (int nt8 = 0; nt8 < 16; nt8++) {         // o2
            uint2 bf = M2v[nt8 * 32 + lane];
            uint32_t d[2][2];
            #pragma unroll
            for (int mi = 0; mi < 2; mi++) {
                d[mi][0] = 0u; d[mi][1] = 0u;
                mma16816h(d[mi], a[mi], bf.x, bf.y);
            }
            const uint32_t swo = ((uint32_t)(i1s ^ (nt8 & 7))) << 4;
            stsm4(abase + (uint32_t)(16 * li0s + nt8) * 256 + swo,
                  d[0][0], d[0][1], d[1][0], d[1][1]);
        }
    }
    __syncthreads();

    // =====================================================================
    // stage B: T2 (256x128) @ M1^T, single pass, f16 acc (64 regs).
    // warp grid 4M x 2N: per warp 4 mi (64 m-rows), 4 jj (64 n-cols).
    // =====================================================================
    uint32_t accb[4][8][2];
    #pragma unroll
    for (int mi = 0; mi < 4; mi++)
        #pragma unroll
        for (int s = 0; s < 8; s++) {
            accb[mi][s][0] = 0u; accb[mi][s][1] = 0u;
        }
    {
        // base addr per mi with the kk-invariant part folded:
        // chunk index = 2kk ^ (hi ^ (ar&7))   [2kk+hi == 2kk^hi, bit-disjoint]
        uint32_t abm[4];
        #pragma unroll
        for (int mi = 0; mi < 4; mi++) {
            const int ar = 64 * mw + 16 * mi + lsel;
            abm[mi] = abase + (uint32_t)ar * 256 +
                      ((uint32_t)(hi ^ (ar & 7)) << 4);
        }
        #pragma unroll
        for (int kk = 0; kk < 8; kk++) {
            uint32_t a[4][4];
            #pragma unroll
            for (int mi = 0; mi < 4; mi++)
                ldsm4(a[mi], abm[mi] ^ ((uint32_t)(2 * kk) << 4));
            #pragma unroll
            for (int jj = 0; jj < 4; jj++) {
                const int nt = 4 * nw + jj;           // 16-wide n-tile
                uint4 bf = M1v[(kk * 8 + nt) * 32 + lane];
                #pragma unroll
                for (int mi = 0; mi < 4; mi++) {
                    mma16816h(accb[mi][2 * jj],     a[mi], bf.x, bf.z);
                    mma16816h(accb[mi][2 * jj + 1], a[mi], bf.y, bf.w);
                }
            }
        }
    }
    __syncthreads();   // all T2 reads done; BUF reusable as T1

    // scatter to T1 (aliased): row = 16*o1 + o2 (256 rows x 256B),
    // chunk = i0, XOR ^(o2&7).
    {
        const int o2v = mrow + 8 * (msel & 1);
        #pragma unroll
        for (int p = 0; p < 2; p++) {
            const int c16 = 4 * mw + 2 * p + (msel >> 1);   // i0
            const uint32_t swo = ((uint32_t)(c16 ^ mrow)) << 4;
            #pragma unroll
            for (int slot = 0; slot < 8; slot++) {
                const int o1 = 8 * nw + slot;
                stsm4(abase + (uint32_t)(16 * o1 + o2v) * 256 + swo,
                      accb[2 * p][slot][0],     accb[2 * p][slot][1],
                      accb[2 * p + 1][slot][0], accb[2 * p + 1][slot][1]);
            }
        }
    }
    __syncthreads();

    // =====================================================================
    // stage C: T1 (256x128) @ M0^T -> f16 accumulators (8 regs)
    // =====================================================================
    uint32_t accc[2][2][2];
    #pragma unroll
    for (int mi = 0; mi < 2; mi++)
        #pragma unroll
        for (int nt = 0; nt < 2; nt++) {
            accc[mi][nt][0] = 0u; accc[mi][nt][1] = 0u;
        }
    #pragma unroll
    for (int ks = 0; ks < 8; ks++) {
        uint32_t a[2][4];
        #pragma unroll
        for (int mi = 0; mi < 2; mi++) {
            const int row = 16 * (w + 8 * mi) + lsel;
            ldsm4(a[mi], abase + (uint32_t)row * 256 +
                         ((uint32_t)((2 * ks + hi) ^ (lsel & 7)) << 4));
        }
        uint4 bf = M0v[ks * 32 + lane];
        #pragma unroll
        for (int mi = 0; mi < 2; mi++) {
            mma16816h(accc[mi][0], a[mi], bf.x, bf.z);
            mma16816h(accc[mi][1], a[mi], bf.y, bf.w);
        }
    }
    __syncthreads();   // T1 reads done; BUF reusable as Ysm

    // ---- epilogue: transpose through Ysm (stride 260), float4 out ----
    #pragma unroll
    for (int mi = 0; mi < 2; mi++) {
        const int row0 = 16 * (w + 8 * mi) + g;   // o1*16+o2
        #pragma unroll
        for (int nt = 0; nt < 2; nt++) {
            const int col0 = 8 * nt + 2 * c;      // o0
            float2 v0 = __half22float2(*(__half2*)&accc[mi][nt][0]);
            float2 v1 = __half22float2(*(__half2*)&accc[mi][nt][1]);
            Ysm[(col0)     * 260 + row0]     = v0.x;
            Ysm[(col0 + 1) * 260 + row0]     = v0.y;
            Ysm[(col0)     * 260 + row0 + 8] = v1.x;
            Ysm[(col0 + 1) * 260 + row0 + 8] = v1.y;
        }
    }
    __syncthreads();

    float* yr = y + (size_t)b * 4096;
    #pragma unroll
    for (int it = 0; it < 4; it++) {
        const int i = 4 * (tid + 256 * it);       // i = o0*256 + row
        const int o0 = i >> 8, row = i & 255;
        float4 v = *(const float4*)&Ysm[o0 * 260 + row];
        float4 bb = *(const float4*)&bias[i];
        v.x += bb.x; v.y += bb.y; v.z += bb.z; v.w += bb.w;
        *(float4*)&yr[i] = v;
    }
}

extern "C" void kernel_launch(void* const* d_in, const int* in_sizes, int n_in,
                              void* d_out, int out_size) {
    const float* x    = (const float*)d_in[0];
    const float* c0   = (const float*)d_in[1];
    const float* c1   = (const float*)d_in[2];
    const float* c2   = (const float*)d_in[3];
    const float* bias = (const float*)d_in[4];
    float* y = (float*)d_out;

    cudaFuncSetAttribute(tt_linear_kernel,
                         cudaFuncAttributeMaxDynamicSharedMemorySize,
                         SMEM_BYTES);

    tt_prep_cores<<<4, 512>>>(c0, c1, c2);
    tt_linear_kernel<<<8192, 256, SMEM_BYTES>>>(x, bias, y);
}